// round 16
// baseline (speedup 1.0000x reference)
#include <cuda_runtime.h>

#define BSZ 4096
#define TSZ 4096
#define NTOT ((long)BSZ * TSZ)
#define HBSZ 2048

#define FIN_BLOCKS 2048
#define FIN_THREADS 256

// raw (unmasked) decoder outputs, [B][T], 16B-aligned for vector stores
__device__ __align__(16) float g_o[NTOT];
// per-block loss partial sums from finalize kernel
__device__ double g_bsum[FIN_BLOCKS];

__device__ __forceinline__ float tanhx(float x) {
    float y; asm("tanh.approx.f32 %0, %1;" : "=f"(y) : "f"(x)); return y;
}

// 4 lanes per chain-pair (roles 0..2 own h0..h2, role 3 mirrors role 2, stores).
// Each lane carries TWO independent chains (X: c, Y: c+2048) so the second
// chain's instructions fill the first chain's latency stalls.
// 8 chain-pairs per warp, 2 warps per block, 128 blocks.
__global__ void __launch_bounds__(64, 1) gru_kernel(
    const float* __restrict__ x, const int* __restrict__ lens,
    const float* __restrict__ eWih, const float* __restrict__ eWhh,
    const float* __restrict__ ebih, const float* __restrict__ ebhh,
    const float* __restrict__ dWih, const float* __restrict__ dWhh,
    const float* __restrict__ dbih, const float* __restrict__ dbhh,
    const float* __restrict__ linW, const float* __restrict__ linb)
{
    const unsigned FULL = 0xFFFFFFFFu;
    const int lane  = threadIdx.x & 31;
    const int warp  = threadIdx.x >> 5;
    const int group = lane >> 2;
    const int role  = lane & 3;
    const int k     = (role == 3) ? 2 : role;
    int kA = k + 1; if (kA == 3) kA = 0;
    int kB = k + 2; if (kB >= 3) kB -= 3;
    const int base = lane & ~3;
    const int srcA = base + kA;
    const int srcB = base + kB;

    const int gwarp  = blockIdx.x * 2 + warp;       // 0..255
    const int chainX = gwarp * 8 + group;           // 0..2047
    const int chainY = chainX + HBSZ;               // 2048..4095
    const int lenX = lens[chainX];
    const int lenY = lens[chainY];
    const int lenX_m1 = lenX - 1;
    const int lenY_m1 = lenY - 1;
    const float* __restrict__ xrowX = x + (long)chainX * TSZ;
    const float* __restrict__ xrowY = x + (long)chainY * TSZ;

    float hX = 0.f, hAX = 0.f, hBX = 0.f, cX = 0.f;
    float hY = 0.f, hAY = 0.f, hBY = 0.f, cY = 0.f;

    // ================= encoder =================
    {
        const float ewr_x = 0.5f * eWih[k];
        const float ewr_b = 0.5f * (ebih[k] + ebhh[k]);
        const float ewr_o = 0.5f * eWhh[k * 3 + k];
        const float ewr_A = 0.5f * eWhh[k * 3 + kA];
        const float ewr_B = 0.5f * eWhh[k * 3 + kB];
        const int zr = 3 + k;
        const float ewz_x = 0.5f * eWih[zr];
        const float ewz_b = 0.5f * (ebih[zr] + ebhh[zr]);
        const float ewz_o = 0.5f * eWhh[zr * 3 + k];
        const float ewz_A = 0.5f * eWhh[zr * 3 + kA];
        const float ewz_B = 0.5f * eWhh[zr * 3 + kB];
        const int nr = 6 + k;
        const float ewn_x  = eWih[nr];
        const float ewn_bi = ebih[nr];
        const float ewn_bh = ebhh[nr];
        const float ewn_o  = eWhh[nr * 3 + k];
        const float ewn_A  = eWhh[nr * 3 + kA];
        const float ewn_B  = eWhh[nr * 3 + kB];

        // one chain's encoder step; called for X then Y (independent -> ptxas interleaves)
        auto enc1 = [&](float& h, float& hA, float& hB, float& c,
                        float xv, int t, int len, int len_m1) {
            float gr = fmaf(xv, ewr_x, ewr_b);
            float gz = fmaf(xv, ewz_x, ewz_b);
            float gn = fmaf(xv, ewn_x, ewn_bi);
            float ar = fmaf(hB, ewr_B, fmaf(hA, ewr_A, fmaf(h, ewr_o, gr)));
            float az = fmaf(hB, ewz_B, fmaf(hA, ewz_A, fmaf(h, ewz_o, gz)));
            float hn = fmaf(hB, ewn_B, fmaf(hA, ewn_A, fmaf(h, ewn_o, ewn_bh)));
            float tr = tanhx(ar);
            float tz = tanhx(az);
            float p = 0.5f * hn;
            float q = fmaf(0.5f, hn, gn);
            float n = tanhx(fmaf(tr, p, q));
            float m_ = fmaf(tz, -0.5f, 0.5f);
            float m  = (t < len) ? m_ : 0.f;     // keep-mask folded into m
            float u  = fmaf(-m, h, h);
            h = fmaf(n, m, u);
            if (t == len_m1) c = h;
            hA = __shfl_sync(FULL, h, srcA);
            hB = __shfl_sync(FULL, h, srcB);
        };

        const int lmax  = lenX > lenY ? lenX : lenY;
        const int wmax  = __reduce_max_sync(FULL, lmax);
        const int wmax4 = (wmax + 3) & ~3;
        for (int t = 0; t < wmax4; t += 4) {
            const float4 xqX = *(const float4*)(xrowX + t);
            const float4 xqY = *(const float4*)(xrowY + t);
            enc1(hX, hAX, hBX, cX, xqX.x, t + 0, lenX, lenX_m1);
            enc1(hY, hAY, hBY, cY, xqY.x, t + 0, lenY, lenY_m1);
            enc1(hX, hAX, hBX, cX, xqX.y, t + 1, lenX, lenX_m1);
            enc1(hY, hAY, hBY, cY, xqY.y, t + 1, lenY, lenY_m1);
            enc1(hX, hAX, hBX, cX, xqX.z, t + 2, lenX, lenX_m1);
            enc1(hY, hAY, hBY, cY, xqY.z, t + 2, lenY, lenY_m1);
            enc1(hX, hAX, hBX, cX, xqX.w, t + 3, lenX, lenX_m1);
            enc1(hY, hAY, hBY, cY, xqY.w, t + 3, lenY, lenY_m1);
        }
    }

    // features = sigmoid(captured own component), then exchange
    hX = fmaf(tanhx(0.5f * cX), 0.5f, 0.5f);
    hY = fmaf(tanhx(0.5f * cY), 0.5f, 0.5f);
    hAX = __shfl_sync(FULL, hX, srcA);
    hBX = __shfl_sync(FULL, hX, srcB);
    hAY = __shfl_sync(FULL, hY, srcA);
    hBY = __shfl_sync(FULL, hY, srcB);

    // ================= decoder (linear layer folded into gates) =================
    {
        const float lw_o = linW[k], lw_A = linW[kA], lw_B = linW[kB], lb = linb[0];

        const float wik = dWih[k];
        const float dr_o = 0.5f * fmaf(wik, lw_o, dWhh[k * 3 + k]);
        const float dr_A = 0.5f * fmaf(wik, lw_A, dWhh[k * 3 + kA]);
        const float dr_B = 0.5f * fmaf(wik, lw_B, dWhh[k * 3 + kB]);
        const float dr_b = 0.5f * (dbih[k] + dbhh[k] + wik * lb);
        const float wiz = dWih[3 + k];
        const float dz_o = 0.5f * fmaf(wiz, lw_o, dWhh[(3 + k) * 3 + k]);
        const float dz_A = 0.5f * fmaf(wiz, lw_A, dWhh[(3 + k) * 3 + kA]);
        const float dz_B = 0.5f * fmaf(wiz, lw_B, dWhh[(3 + k) * 3 + kB]);
        const float dz_b = 0.5f * (dbih[3 + k] + dbhh[3 + k] + wiz * lb);
        const float win = dWih[6 + k];
        const float di_o = win * lw_o;
        const float di_A = win * lw_A;
        const float di_B = win * lw_B;
        const float di_b = fmaf(win, lb, dbih[6 + k]);
        const float dn_o = dWhh[(6 + k) * 3 + k];
        const float dn_A = dWhh[(6 + k) * 3 + kA];
        const float dn_B = dWhh[(6 + k) * 3 + kB];
        const float dn_b = dbhh[6 + k];

        float* __restrict__ growX = g_o + (long)chainX * TSZ;
        float* __restrict__ growY = g_o + (long)chainY * TSZ;

        auto dec1 = [&](float& h, float& hA, float& hB) -> float {
            float ar = fmaf(hB, dr_B, fmaf(hA, dr_A, fmaf(h, dr_o, dr_b)));
            float az = fmaf(hB, dz_B, fmaf(hA, dz_A, fmaf(h, dz_o, dz_b)));
            float hn = fmaf(hB, dn_B, fmaf(hA, dn_A, fmaf(h, dn_o, dn_b)));
            float gi = fmaf(hB, di_B, fmaf(hA, di_A, fmaf(h, di_o, di_b)));
            float tr = tanhx(ar);
            float tz = tanhx(az);
            float p = 0.5f * hn;
            float q = fmaf(0.5f, hn, gi);
            float n = tanhx(fmaf(tr, p, q));
            float m = fmaf(tz, -0.5f, 0.5f);
            float u = fmaf(-m, h, h);
            h = fmaf(n, m, u);
            hA = __shfl_sync(FULL, h, srcA);
            hB = __shfl_sync(FULL, h, srcB);
            return fmaf(hB, lw_B, fmaf(hA, lw_A, fmaf(h, lw_o, lb)));
        };

        // step 0 (inp = 0): unfolded, raw weights from global
        auto dec0 = [&](float& h, float& hA, float& hB) -> float {
            float ar = 0.5f * (dbih[k] + dbhh[k]
                     + fmaf(hB, dWhh[k * 3 + kB], fmaf(hA, dWhh[k * 3 + kA], h * dWhh[k * 3 + k])));
            float az = 0.5f * (dbih[3 + k] + dbhh[3 + k]
                     + fmaf(hB, dWhh[(3 + k) * 3 + kB], fmaf(hA, dWhh[(3 + k) * 3 + kA], h * dWhh[(3 + k) * 3 + k])));
            float hn = dbhh[6 + k]
                     + fmaf(hB, dWhh[(6 + k) * 3 + kB], fmaf(hA, dWhh[(6 + k) * 3 + kA], h * dWhh[(6 + k) * 3 + k]));
            float r = fmaf(tanhx(ar), 0.5f, 0.5f);
            float n = tanhx(fmaf(r, hn, dbih[6 + k]));
            float m = fmaf(tanhx(az), -0.5f, 0.5f);
            float u = fmaf(-m, h, h);
            h = fmaf(n, m, u);
            hA = __shfl_sync(FULL, h, srcA);
            hB = __shfl_sync(FULL, h, srcB);
            return fmaf(hB, lw_B, fmaf(hA, lw_A, fmaf(h, lw_o, lb)));
        };

        // ---- quad 0: step 0 unfolded + steps 1..3 ----
        {
            float oX0 = dec0(hX, hAX, hBX);
            float oY0 = dec0(hY, hAY, hBY);
            float oX1 = dec1(hX, hAX, hBX);
            float oY1 = dec1(hY, hAY, hBY);
            float oX2 = dec1(hX, hAX, hBX);
            float oY2 = dec1(hY, hAY, hBY);
            float oX3 = dec1(hX, hAX, hBX);
            float oY3 = dec1(hY, hAY, hBY);
            if (role == 3) {
                *(float4*)(growX + 0) = make_float4(oX0, oX1, oX2, oX3);
                *(float4*)(growY + 0) = make_float4(oY0, oY1, oY2, oY3);
            }
        }
        // ---- quads t = 4..4092 ----
        for (int t = 4; t < TSZ; t += 4) {
            float oX0 = dec1(hX, hAX, hBX);
            float oY0 = dec1(hY, hAY, hBY);
            float oX1 = dec1(hX, hAX, hBX);
            float oY1 = dec1(hY, hAY, hBY);
            float oX2 = dec1(hX, hAX, hBX);
            float oY2 = dec1(hY, hAY, hBY);
            float oX3 = dec1(hX, hAX, hBX);
            float oY3 = dec1(hY, hAY, hBY);
            if (role == 3) {
                *(float4*)(growX + t) = make_float4(oX0, oX1, oX2, oX3);
                *(float4*)(growY + t) = make_float4(oY0, oY1, oY2, oY3);
            }
        }
    }
}

// Fused elementwise pass: xpad, masked output copy, loss partials.
// Quad-per-thread: float4 loads, scalar stores (targets are 4B-aligned only).
__global__ void finalize_kernel(const float* __restrict__ x,
                                const int* __restrict__ lens,
                                float* __restrict__ xpad,
                                float* __restrict__ outmasked)
{
    __shared__ double s[FIN_THREADS];
    const int tid = threadIdx.x;
    const long nquads = NTOT / 4;
    float acc = 0.f;
    for (long q = (long)blockIdx.x * FIN_THREADS + tid; q < nquads;
         q += (long)FIN_BLOCKS * FIN_THREADS) {
        long idx = q * 4;
        int b  = (int)(idx >> 12);
        int t0 = (int)(idx & (TSZ - 1));
        int L  = lens[b];
        float4 xq = *(const float4*)(x + idx);
        float4 oq = *(const float4*)(g_o + idx);
        float xm0 = (t0 + 0 < L) ? xq.x : 0.f;
        float xm1 = (t0 + 1 < L) ? xq.y : 0.f;
        float xm2 = (t0 + 2 < L) ? xq.z : 0.f;
        float xm3 = (t0 + 3 < L) ? xq.w : 0.f;
        float om0 = (t0 + 0 < L) ? oq.x : 0.f;
        float om1 = (t0 + 1 < L) ? oq.y : 0.f;
        float om2 = (t0 + 2 < L) ? oq.z : 0.f;
        float om3 = (t0 + 3 < L) ? oq.w : 0.f;
        xpad[idx + 0] = xm0; xpad[idx + 1] = xm1;
        xpad[idx + 2] = xm2; xpad[idx + 3] = xm3;
        outmasked[idx + 0] = om0; outmasked[idx + 1] = om1;
        outmasked[idx + 2] = om2; outmasked[idx + 3] = om3;
        float d0 = xm0 - om0, d1 = xm1 - om1, d2 = xm2 - om2, d3 = xm3 - om3;
        acc = fmaf(d0, d0, acc);
        acc = fmaf(d1, d1, acc);
        acc = fmaf(d2, d2, acc);
        acc = fmaf(d3, d3, acc);
    }
    s[tid] = (double)acc;
    __syncthreads();
    for (int off = FIN_THREADS / 2; off > 0; off >>= 1) {
        if (tid < off) s[tid] += s[tid + off];
        __syncthreads();
    }
    if (tid == 0) g_bsum[blockIdx.x] = s[0];
}

// Deterministic fixed-order reduction of block partials -> scalar loss
__global__ void loss_kernel(float* __restrict__ out_loss)
{
    __shared__ double s[512];
    int tid = threadIdx.x;
    double a = g_bsum[tid] + g_bsum[tid + 512] + g_bsum[tid + 1024] + g_bsum[tid + 1536];
    s[tid] = a;
    __syncthreads();
    for (int off = 256; off > 0; off >>= 1) {
        if (tid < off) s[tid] += s[tid + off];
        __syncthreads();
    }
    if (tid == 0) out_loss[0] = (float)(s[0] / ((double)BSZ * (double)TSZ));
}

extern "C" void kernel_launch(void* const* d_in, const int* in_sizes, int n_in,
                              void* d_out, int out_size)
{
    const float* x    = (const float*)d_in[0];
    const int*   lens = (const int*)  d_in[1];
    const float* eWih = (const float*)d_in[2];
    const float* eWhh = (const float*)d_in[3];
    const float* ebih = (const float*)d_in[4];
    const float* ebhh = (const float*)d_in[5];
    const float* dWih = (const float*)d_in[6];
    const float* dWhh = (const float*)d_in[7];
    const float* dbih = (const float*)d_in[8];
    const float* dbhh = (const float*)d_in[9];
    const float* linW = (const float*)d_in[10];
    const float* linb = (const float*)d_in[11];

    float* out    = (float*)d_out;
    float* loss   = out;                       // [1]
    float* xpad   = out + 1;                   // [B*T]
    float* output = out + 1 + NTOT;            // [B*T]

    gru_kernel<<<128, 64>>>(x, lens, eWih, eWhh, ebih, ebhh,
                            dWih, dWhh, dbih, dbhh, linW, linb);
    finalize_kernel<<<FIN_BLOCKS, FIN_THREADS>>>(x, lens, xpad, output);
    loss_kernel<<<1, 512>>>(loss);
}

// round 17
// speedup vs baseline: 1.2158x; 1.2158x over previous
#include <cuda_runtime.h>

#define BSZ 4096
#define TSZ 4096
#define NTOT ((long)BSZ * TSZ)

#define GRU_THREADS 512          // warps 0..3 recurrence, all 16 warps finalize
#define CH_PER_BLK 32

// raw (unmasked) decoder outputs, [B][T], 16B-aligned for vector stores
__device__ __align__(16) float g_o[NTOT];
// per-block loss partial sums
__device__ double g_bsum[128];

__device__ __forceinline__ float tanhx(float x) {
    float y; asm("tanh.approx.f32 %0, %1;" : "=f"(y) : "f"(x)); return y;
}

// Phase 1 (warps 0..3): lane-split recurrence, 4 lanes per chain, 8 chains/warp.
// Phase 2 (all 512 threads): stream finalize of the block's own 32 chains.
__global__ void __launch_bounds__(GRU_THREADS, 1) gru_kernel(
    const float* __restrict__ x, const int* __restrict__ lens,
    const float* __restrict__ eWih, const float* __restrict__ eWhh,
    const float* __restrict__ ebih, const float* __restrict__ ebhh,
    const float* __restrict__ dWih, const float* __restrict__ dWhh,
    const float* __restrict__ dbih, const float* __restrict__ dbhh,
    const float* __restrict__ linW, const float* __restrict__ linb,
    float* __restrict__ out_xpad, float* __restrict__ out_output)
{
    const unsigned FULL = 0xFFFFFFFFu;
    const int tid   = threadIdx.x;
    const int lane  = tid & 31;
    const int warp  = tid >> 5;

    if (warp < 4) {
        const int group = lane >> 2;
        const int role  = lane & 3;
        const int k     = (role == 3) ? 2 : role;
        int kA = k + 1; if (kA == 3) kA = 0;
        int kB = k + 2; if (kB >= 3) kB -= 3;
        const int base = lane & ~3;
        const int srcA = base + kA;
        const int srcB = base + kB;

        const int chain = (blockIdx.x * 4 + warp) * 8 + group;
        const int len   = lens[chain];
        const int len_m1 = len - 1;
        const float* __restrict__ xrow = x + (long)chain * TSZ;

        float h = 0.f, hA = 0.f, hB = 0.f;
        float c = 0.f;                     // captured own component at t == len-1

        // ================= encoder =================
        {
            const float ewr_x = 0.5f * eWih[k];
            const float ewr_b = 0.5f * (ebih[k] + ebhh[k]);
            const float ewr_o = 0.5f * eWhh[k * 3 + k];
            const float ewr_A = 0.5f * eWhh[k * 3 + kA];
            const float ewr_B = 0.5f * eWhh[k * 3 + kB];
            const int zr = 3 + k;
            const float ewz_x = 0.5f * eWih[zr];
            const float ewz_b = 0.5f * (ebih[zr] + ebhh[zr]);
            const float ewz_o = 0.5f * eWhh[zr * 3 + k];
            const float ewz_A = 0.5f * eWhh[zr * 3 + kA];
            const float ewz_B = 0.5f * eWhh[zr * 3 + kB];
            const int nr = 6 + k;
            const float ewn_x  = eWih[nr];
            const float ewn_bi = ebih[nr];
            const float ewn_bh = ebhh[nr];
            const float ewn_o  = eWhh[nr * 3 + k];
            const float ewn_A  = eWhh[nr * 3 + kA];
            const float ewn_B  = eWhh[nr * 3 + kB];

            auto enc_step = [&](float xv, int t) {
                float gr = fmaf(xv, ewr_x, ewr_b);
                float gz = fmaf(xv, ewz_x, ewz_b);
                float gn = fmaf(xv, ewn_x, ewn_bi);
                float ar = fmaf(hB, ewr_B, fmaf(hA, ewr_A, fmaf(h, ewr_o, gr)));
                float az = fmaf(hB, ewz_B, fmaf(hA, ewz_A, fmaf(h, ewz_o, gz)));
                float hn = fmaf(hB, ewn_B, fmaf(hA, ewn_A, fmaf(h, ewn_o, ewn_bh)));
                float tr = tanhx(ar);
                float tz = tanhx(az);
                float p = 0.5f * hn;
                float q = fmaf(0.5f, hn, gn);
                float n = tanhx(fmaf(tr, p, q));
                float m_ = fmaf(tz, -0.5f, 0.5f);
                float m  = (t < len) ? m_ : 0.f;   // keep-mask folded into m
                float u  = fmaf(-m, h, h);
                h = fmaf(n, m, u);
                if (t == len_m1) c = h;
                hA = __shfl_sync(FULL, h, srcA);
                hB = __shfl_sync(FULL, h, srcB);
            };

            const int wmax  = __reduce_max_sync(FULL, len);
            const int wmax4 = (wmax + 3) & ~3;
            for (int t = 0; t < wmax4; t += 4) {
                const float4 xq = *(const float4*)(xrow + t);
                enc_step(xq.x, t + 0);
                enc_step(xq.y, t + 1);
                enc_step(xq.z, t + 2);
                enc_step(xq.w, t + 3);
            }
        }

        // features = sigmoid(captured own component), then exchange
        h  = fmaf(tanhx(0.5f * c), 0.5f, 0.5f);
        hA = __shfl_sync(FULL, h, srcA);
        hB = __shfl_sync(FULL, h, srcB);

        // ================= decoder (linear layer folded into gates) =================
        {
            const float lw_o = linW[k], lw_A = linW[kA], lw_B = linW[kB], lb = linb[0];

            const float wik = dWih[k];
            const float dr_o = 0.5f * fmaf(wik, lw_o, dWhh[k * 3 + k]);
            const float dr_A = 0.5f * fmaf(wik, lw_A, dWhh[k * 3 + kA]);
            const float dr_B = 0.5f * fmaf(wik, lw_B, dWhh[k * 3 + kB]);
            const float dr_b = 0.5f * (dbih[k] + dbhh[k] + wik * lb);
            const float wiz = dWih[3 + k];
            const float dz_o = 0.5f * fmaf(wiz, lw_o, dWhh[(3 + k) * 3 + k]);
            const float dz_A = 0.5f * fmaf(wiz, lw_A, dWhh[(3 + k) * 3 + kA]);
            const float dz_B = 0.5f * fmaf(wiz, lw_B, dWhh[(3 + k) * 3 + kB]);
            const float dz_b = 0.5f * (dbih[3 + k] + dbhh[3 + k] + wiz * lb);
            const float win = dWih[6 + k];
            const float di_o = win * lw_o;
            const float di_A = win * lw_A;
            const float di_B = win * lw_B;
            const float di_b = fmaf(win, lb, dbih[6 + k]);
            const float dn_o = dWhh[(6 + k) * 3 + k];
            const float dn_A = dWhh[(6 + k) * 3 + kA];
            const float dn_B = dWhh[(6 + k) * 3 + kB];
            const float dn_b = dbhh[6 + k];

            float* __restrict__ grow = g_o + (long)chain * TSZ;

            auto dec_step = [&]() -> float {
                float ar = fmaf(hB, dr_B, fmaf(hA, dr_A, fmaf(h, dr_o, dr_b)));
                float az = fmaf(hB, dz_B, fmaf(hA, dz_A, fmaf(h, dz_o, dz_b)));
                float hn = fmaf(hB, dn_B, fmaf(hA, dn_A, fmaf(h, dn_o, dn_b)));
                float gi = fmaf(hB, di_B, fmaf(hA, di_A, fmaf(h, di_o, di_b)));
                float tr = tanhx(ar);
                float tz = tanhx(az);
                float p = 0.5f * hn;
                float q = fmaf(0.5f, hn, gi);
                float n = tanhx(fmaf(tr, p, q));
                float m = fmaf(tz, -0.5f, 0.5f);
                float u = fmaf(-m, h, h);
                h = fmaf(n, m, u);
                hA = __shfl_sync(FULL, h, srcA);
                hB = __shfl_sync(FULL, h, srcB);
                return fmaf(hB, lw_B, fmaf(hA, lw_A, fmaf(h, lw_o, lb)));
            };

            // ---- step 0 (inp = 0): unfolded, raw weights from global ----
            float o_first;
            {
                float ar = 0.5f * (dbih[k] + dbhh[k]
                         + fmaf(hB, dWhh[k * 3 + kB], fmaf(hA, dWhh[k * 3 + kA], h * dWhh[k * 3 + k])));
                float az = 0.5f * (dbih[3 + k] + dbhh[3 + k]
                         + fmaf(hB, dWhh[(3 + k) * 3 + kB], fmaf(hA, dWhh[(3 + k) * 3 + kA], h * dWhh[(3 + k) * 3 + k])));
                float hn = dbhh[6 + k]
                         + fmaf(hB, dWhh[(6 + k) * 3 + kB], fmaf(hA, dWhh[(6 + k) * 3 + kA], h * dWhh[(6 + k) * 3 + k]));
                float r = fmaf(tanhx(ar), 0.5f, 0.5f);
                float n = tanhx(fmaf(r, hn, dbih[6 + k]));
                float m = fmaf(tanhx(az), -0.5f, 0.5f);
                float u = fmaf(-m, h, h);
                h = fmaf(n, m, u);
                hA = __shfl_sync(FULL, h, srcA);
                hB = __shfl_sync(FULL, h, srcB);
                o_first = fmaf(hB, lw_B, fmaf(hA, lw_A, fmaf(h, lw_o, lb)));
            }
            // ---- steps 1..3, complete first store group ----
            {
                float o1 = dec_step();
                float o2 = dec_step();
                float o3 = dec_step();
                if (role == 3)
                    *(float4*)(grow + 0) = make_float4(o_first, o1, o2, o3);
            }
            // ---- steps 4..4095: 1023 quads ----
            for (int t = 4; t < TSZ; t += 4) {
                float o0 = dec_step();
                float o1 = dec_step();
                float o2 = dec_step();
                float o3 = dec_step();
                if (role == 3)
                    *(float4*)(grow + t) = make_float4(o0, o1, o2, o3);
            }
        }
    }

    // ================= phase 2: block-local finalize of its 32 chains =================
    __syncthreads();
    {
        __shared__ double s[GRU_THREADS];
        const long regbase = (long)blockIdx.x * CH_PER_BLK * TSZ;   // element base
        const int  nquads  = CH_PER_BLK * TSZ / 4;                  // 32768
        float acc = 0.f;
        for (int q = tid; q < nquads; q += GRU_THREADS) {
            long idx = regbase + (long)q * 4;
            int b  = (int)(idx >> 12);
            int t0 = (int)(idx & (TSZ - 1));
            int L  = lens[b];
            float4 xq = *(const float4*)(x + idx);
            float4 oq = *(const float4*)(g_o + idx);
            float xm0 = (t0 + 0 < L) ? xq.x : 0.f;
            float xm1 = (t0 + 1 < L) ? xq.y : 0.f;
            float xm2 = (t0 + 2 < L) ? xq.z : 0.f;
            float xm3 = (t0 + 3 < L) ? xq.w : 0.f;
            float om0 = (t0 + 0 < L) ? oq.x : 0.f;
            float om1 = (t0 + 1 < L) ? oq.y : 0.f;
            float om2 = (t0 + 2 < L) ? oq.z : 0.f;
            float om3 = (t0 + 3 < L) ? oq.w : 0.f;
            out_xpad[idx + 0] = xm0; out_xpad[idx + 1] = xm1;
            out_xpad[idx + 2] = xm2; out_xpad[idx + 3] = xm3;
            out_output[idx + 0] = om0; out_output[idx + 1] = om1;
            out_output[idx + 2] = om2; out_output[idx + 3] = om3;
            float d0 = xm0 - om0, d1 = xm1 - om1, d2 = xm2 - om2, d3 = xm3 - om3;
            acc = fmaf(d0, d0, acc);
            acc = fmaf(d1, d1, acc);
            acc = fmaf(d2, d2, acc);
            acc = fmaf(d3, d3, acc);
        }
        s[tid] = (double)acc;
        __syncthreads();
        for (int off = GRU_THREADS / 2; off > 0; off >>= 1) {
            if (tid < off) s[tid] += s[tid + off];
            __syncthreads();
        }
        if (tid == 0) g_bsum[blockIdx.x] = s[0];
    }
}

// Deterministic fixed-order reduction of the 128 block partials -> scalar loss
__global__ void loss_kernel(float* __restrict__ out_loss)
{
    __shared__ double s[128];
    int tid = threadIdx.x;
    s[tid] = g_bsum[tid];
    __syncthreads();
    for (int off = 64; off > 0; off >>= 1) {
        if (tid < off) s[tid] += s[tid + off];
        __syncthreads();
    }
    if (tid == 0) out_loss[0] = (float)(s[0] / ((double)BSZ * (double)TSZ));
}

extern "C" void kernel_launch(void* const* d_in, const int* in_sizes, int n_in,
                              void* d_out, int out_size)
{
    const float* x    = (const float*)d_in[0];
    const int*   lens = (const int*)  d_in[1];
    const float* eWih = (const float*)d_in[2];
    const float* eWhh = (const float*)d_in[3];
    const float* ebih = (const float*)d_in[4];
    const float* ebhh = (const float*)d_in[5];
    const float* dWih = (const float*)d_in[6];
    const float* dWhh = (const float*)d_in[7];
    const float* dbih = (const float*)d_in[8];
    const float* dbhh = (const float*)d_in[9];
    const float* linW = (const float*)d_in[10];
    const float* linb = (const float*)d_in[11];

    float* out    = (float*)d_out;
    float* loss   = out;                       // [1]
    float* xpad   = out + 1;                   // [B*T]
    float* output = out + 1 + NTOT;            // [B*T]

    gru_kernel<<<128, GRU_THREADS>>>(x, lens, eWih, eWhh, ebih, ebhh,
                                     dWih, dWhh, dbih, dbhh, linW, linb,
                                     xpad, output);
    loss_kernel<<<1, 128>>>(loss);
}